// round 1
// baseline (speedup 1.0000x reference)
#include <cuda_runtime.h>
#include <stdint.h>

// TopK mask: out = x * (x in top-k of its row), ties broken by lowest index.
// One CTA (256 threads) per row of 4096 fp32. Exact count-based radix select
// over order-preserving uint32 keys; single full-data multiway sweep in the
// common case, rare fallbacks keep it exact for arbitrary data.

#define F_DIM 4096
#define TPB   256
#define VPT   16      // values per thread (4 x uint4)
#define CAP   128     // candidate buffer capacity

// monotone float->uint key (larger key == larger float)
static __device__ __forceinline__ unsigned f2key(unsigned u) {
    return u ^ ((unsigned)((int)u >> 31) | 0x80000000u);
}
// inverse
static __device__ __forceinline__ unsigned key2u(unsigned k) {
    return (k & 0x80000000u) ? (k ^ 0x80000000u) : ~k;
}

__global__ __launch_bounds__(TPB, 1)
void topk_mask_kernel(const float* __restrict__ x,
                      const int*   __restrict__ kptr,
                      int kfallback,
                      float* __restrict__ out)
{
    const int tid  = threadIdx.x;
    const int lane = tid & 31;
    const int wid  = tid >> 5;
    const size_t row = blockIdx.x;

    __shared__ unsigned s_warp[8][4];   // per-warp partial counts
    __shared__ unsigned s_ctrl[8];      // [0]=Kstar [2]=c_ge [3]=c_gt [7]=cand counter
    __shared__ unsigned s_ckey[CAP];    // compacted candidate keys

    const uint4* __restrict__ xr   = reinterpret_cast<const uint4*>(x)   + row * (F_DIM / 4);
    uint4*       __restrict__ orow = reinterpret_cast<uint4*>(out)       + row * (F_DIM / 4);

    // ---- load 16 values / thread, convert to keys ----
    // element e = i*4+j  -> column  (i<<10) + (tid<<2) + j   (i = e>>2, j = e&3)
    unsigned key[VPT];
    {
        uint4 a0 = xr[tid];
        uint4 a1 = xr[tid + 256];
        uint4 a2 = xr[tid + 512];
        uint4 a3 = xr[tid + 768];
        key[ 0]=f2key(a0.x); key[ 1]=f2key(a0.y); key[ 2]=f2key(a0.z); key[ 3]=f2key(a0.w);
        key[ 4]=f2key(a1.x); key[ 5]=f2key(a1.y); key[ 6]=f2key(a1.z); key[ 7]=f2key(a1.w);
        key[ 8]=f2key(a2.x); key[ 9]=f2key(a2.y); key[10]=f2key(a2.z); key[11]=f2key(a2.w);
        key[12]=f2key(a3.x); key[13]=f2key(a3.y); key[14]=f2key(a3.z); key[15]=f2key(a3.w);
    }

    const int kv = (kptr != nullptr) ? *kptr : kfallback;

    // trivial cases (uniform across block)
    if (kv <= 0) {
        uint4 z; z.x = z.y = z.z = z.w = 0u;
        #pragma unroll
        for (int i = 0; i < 4; ++i) orow[tid + i * 256] = z;
        return;
    }
    const unsigned K = (unsigned)kv;

    unsigned Kstar = 0u;
    unsigned Ccut  = 0xFFFFFFFFu;

    if (K < (unsigned)F_DIM) {
        // bracket [lo, lo+w-1] contains the K-th largest key.
        // invariant: C(lo) = cnt_lo >= K > cnt_hi1 = C(lo+w)
        unsigned lo = 0u, cnt_lo = F_DIM, cnt_hi1 = 0u;
        unsigned w = 0u;              // set after first sweep
        unsigned q = 1u << 30;        // quarter of current width (first width = 2^32)

        // ---- up to 3 multiway (2-bit) full-data sweeps ----
        #pragma unroll 1
        for (int s = 0; s < 3; ++s) {
            if (cnt_lo - cnt_hi1 <= CAP) break;           // uniform
            unsigned t1 = lo + q, t2 = lo + 2u * q, t3 = lo + 3u * q;
            unsigned c1 = 0, c2 = 0, c3 = 0;
            #pragma unroll
            for (int e = 0; e < VPT; ++e) {
                c1 += (key[e] >= t1);
                c2 += (key[e] >= t2);
                c3 += (key[e] >= t3);
            }
            c1 = __reduce_add_sync(0xffffffffu, c1);
            c2 = __reduce_add_sync(0xffffffffu, c2);
            c3 = __reduce_add_sync(0xffffffffu, c3);
            if (lane == 0) { s_warp[wid][0] = c1; s_warp[wid][1] = c2; s_warp[wid][2] = c3; }
            __syncthreads();
            unsigned C1 = 0, C2 = 0, C3 = 0;
            #pragma unroll
            for (int u2 = 0; u2 < 8; ++u2) { C1 += s_warp[u2][0]; C2 += s_warp[u2][1]; C3 += s_warp[u2][2]; }
            __syncthreads();
            if      (C3 >= K) { lo = t3; cnt_lo = C3; }
            else if (C2 >= K) { lo = t2; cnt_lo = C2; cnt_hi1 = C3; }
            else if (C1 >= K) { lo = t1; cnt_lo = C1; cnt_hi1 = C2; }
            else              {                      cnt_hi1 = C1; }
            w = q;
            q >>= 2;
        }

        // ---- rare: 1-bit full-data sweeps until candidates fit ----
        #pragma unroll 1
        while (cnt_lo - cnt_hi1 > CAP && w > 1u) {
            unsigned tm = lo + (w >> 1);
            unsigned c = 0;
            #pragma unroll
            for (int e = 0; e < VPT; ++e) c += (key[e] >= tm);
            c = __reduce_add_sync(0xffffffffu, c);
            if (lane == 0) s_warp[wid][0] = c;
            __syncthreads();
            unsigned C = 0;
            #pragma unroll
            for (int u2 = 0; u2 < 8; ++u2) C += s_warp[u2][0];
            __syncthreads();
            if (C >= K) { lo = tm; cnt_lo = C; } else { cnt_hi1 = C; }
            w >>= 1;
        }

        unsigned c_ge, c_gt;
        if (w <= 1u) {
            Kstar = lo; c_ge = cnt_lo; c_gt = cnt_hi1;
        } else {
            // ---- compact candidates (keys in [lo, lo+w-1]) into smem ----
            if (tid == 0) s_ctrl[7] = 0u;
            __syncthreads();
            unsigned hi = lo + (w - 1u);
            #pragma unroll
            for (int e = 0; e < VPT; ++e) {
                bool in = (key[e] >= lo) && (key[e] <= hi);
                unsigned m = __ballot_sync(0xffffffffu, in);
                unsigned base = 0u;
                if (lane == 0) base = atomicAdd(&s_ctrl[7], (unsigned)__popc(m));
                base = __shfl_sync(0xffffffffu, base, 0);
                if (in) {
                    unsigned p = base + (unsigned)__popc(m & ((1u << lane) - 1u));
                    if (p < CAP) s_ckey[p] = key[e];
                }
            }
            __syncthreads();

            // ---- warp 0 finishes the bisection on the candidates ----
            if (wid == 0) {
                unsigned n_c = s_ctrl[7];
                unsigned A   = cnt_hi1;     // count strictly above bracket
                unsigned ck[CAP / 32];
                #pragma unroll
                for (int j = 0; j < CAP / 32; ++j) {
                    unsigned idx = (unsigned)lane + 32u * j;
                    ck[j] = (idx < n_c) ? s_ckey[idx] : 0u;  // 0 never passes (tm >= 1)
                }
                unsigned llo = lo, ww = w, clo = cnt_lo, chi = cnt_hi1;
                #pragma unroll 1
                while (ww > 1u) {
                    unsigned tm = llo + (ww >> 1);
                    unsigned c = 0;
                    #pragma unroll
                    for (int j = 0; j < CAP / 32; ++j) c += (ck[j] >= tm);
                    c = __reduce_add_sync(0xffffffffu, c) + A;
                    if (c >= K) { llo = tm; clo = c; } else { chi = c; }
                    ww >>= 1;
                }
                if (lane == 0) { s_ctrl[0] = llo; s_ctrl[2] = clo; s_ctrl[3] = chi; }
            }
            __syncthreads();
            Kstar = s_ctrl[0]; c_ge = s_ctrl[2]; c_gt = s_ctrl[3];
        }

        // ---- tie truncation (rare): keep lowest-index equals only ----
        unsigned budget = K - c_gt;          // >= 1
        unsigned c_eq   = c_ge - c_gt;       // >= budget
        if (budget < c_eq) {
            int loB = 0, hiB = F_DIM - 1;
            #pragma unroll 1
            while (loB < hiB) {
                int mid = (loB + hiB) >> 1;
                unsigned c = 0;
                #pragma unroll
                for (int e = 0; e < VPT; ++e) {
                    int col = ((e >> 2) << 10) + (tid << 2) + (e & 3);
                    c += (key[e] == Kstar && col <= mid) ? 1u : 0u;
                }
                c = __reduce_add_sync(0xffffffffu, c);
                if (lane == 0) s_warp[wid][0] = c;
                __syncthreads();
                unsigned Ct = 0;
                #pragma unroll
                for (int u2 = 0; u2 < 8; ++u2) Ct += s_warp[u2][0];
                __syncthreads();
                if (Ct >= budget) hiB = mid; else loB = mid + 1;
            }
            Ccut = (unsigned)loB;
        }
    }
    // K >= F: Kstar=0, Ccut=max -> keep everything.

    // ---- write: keep iff key > Kstar, or key == Kstar and col <= Ccut ----
    #pragma unroll
    for (int i = 0; i < 4; ++i) {
        unsigned col0 = (unsigned)((i << 10) + (tid << 2));
        uint4 v;
        {
            unsigned kk = key[i * 4 + 0];
            bool keep = (kk > Kstar) || (kk == Kstar && (col0 + 0u) <= Ccut);
            v.x = keep ? key2u(kk) : 0u;
        }
        {
            unsigned kk = key[i * 4 + 1];
            bool keep = (kk > Kstar) || (kk == Kstar && (col0 + 1u) <= Ccut);
            v.y = keep ? key2u(kk) : 0u;
        }
        {
            unsigned kk = key[i * 4 + 2];
            bool keep = (kk > Kstar) || (kk == Kstar && (col0 + 2u) <= Ccut);
            v.z = keep ? key2u(kk) : 0u;
        }
        {
            unsigned kk = key[i * 4 + 3];
            bool keep = (kk > Kstar) || (kk == Kstar && (col0 + 3u) <= Ccut);
            v.w = keep ? key2u(kk) : 0u;
        }
        orow[tid + i * 256] = v;
    }
}

extern "C" void kernel_launch(void* const* d_in, const int* in_sizes, int n_in,
                              void* d_out, int out_size)
{
    const float* x  = (const float*)d_in[0];
    const int*   kp = (n_in >= 2) ? (const int*)d_in[1] : nullptr;
    float* out = (float*)d_out;

    int B = in_sizes[0] / F_DIM;
    topk_mask_kernel<<<B, TPB>>>(x, kp, 64, out);
}

// round 4
// speedup vs baseline: 1.3437x; 1.3437x over previous
#include <cuda_runtime.h>
#include <stdint.h>

// TopK mask: out = x * (x in top-k of its row), ties -> lowest index.
// One CTA (256 thr) per row of 4096 fp32. Exact count-based radix select.
// R2: no register residency of the row (re-read from L1/L2 per phase) to
// maximize occupancy; block-parallel rank selection replaces serial warp-0
// bisection.

#define F_DIM 4096
#define TPB   256
#define CAP   128

// monotone float->uint key (larger key == larger float)
static __device__ __forceinline__ unsigned f2key(unsigned u) {
    return u ^ ((unsigned)((int)u >> 31) | 0x80000000u);
}

// load this thread's 16 raw words (coalesced uint4 x4)
static __device__ __forceinline__ void load_row(const uint4* __restrict__ xr, int tid,
                                                uint4& a0, uint4& a1, uint4& a2, uint4& a3) {
    a0 = __ldg(xr + tid);
    a1 = __ldg(xr + tid + 256);
    a2 = __ldg(xr + tid + 512);
    a3 = __ldg(xr + tid + 768);
}

static __device__ __forceinline__ void to_keys(const uint4& a0, const uint4& a1,
                                               const uint4& a2, const uint4& a3,
                                               unsigned key[16]) {
    key[ 0]=f2key(a0.x); key[ 1]=f2key(a0.y); key[ 2]=f2key(a0.z); key[ 3]=f2key(a0.w);
    key[ 4]=f2key(a1.x); key[ 5]=f2key(a1.y); key[ 6]=f2key(a1.z); key[ 7]=f2key(a1.w);
    key[ 8]=f2key(a2.x); key[ 9]=f2key(a2.y); key[10]=f2key(a2.z); key[11]=f2key(a2.w);
    key[12]=f2key(a3.x); key[13]=f2key(a3.y); key[14]=f2key(a3.z); key[15]=f2key(a3.w);
}

__global__ __launch_bounds__(TPB, 6)
void topk_mask_kernel(const float* __restrict__ x,
                      const int*   __restrict__ kptr,
                      int kfallback,
                      float* __restrict__ out)
{
    const int tid  = threadIdx.x;
    const int lane = tid & 31;
    const int wid  = tid >> 5;
    const size_t row = blockIdx.x;

    __shared__ unsigned s_warp[8][4];   // per-warp partial counts
    __shared__ unsigned s_ctrl[8];      // [0]=Kstar [2]=c_ge [3]=c_gt [7]=cand counter
    __shared__ unsigned s_ckey[CAP];    // compacted candidate keys

    const uint4* __restrict__ xr   = reinterpret_cast<const uint4*>(x) + row * (F_DIM / 4);
    uint4*       __restrict__ orow = reinterpret_cast<uint4*>(out)     + row * (F_DIM / 4);

    const int kv = (kptr != nullptr) ? *kptr : kfallback;

    if (kv <= 0) {
        uint4 z; z.x = z.y = z.z = z.w = 0u;
        #pragma unroll
        for (int i = 0; i < 4; ++i) orow[tid + i * 256] = z;
        return;
    }
    if (kv >= F_DIM) {
        uint4 a0, a1, a2, a3; load_row(xr, tid, a0, a1, a2, a3);
        orow[tid      ] = a0; orow[tid + 256] = a1;
        orow[tid + 512] = a2; orow[tid + 768] = a3;
        return;
    }
    const unsigned K = (unsigned)kv;

    // bracket [lo, lo + 2^shift - 1] contains the K-th largest key.
    // invariant: C(lo)=cnt_lo >= K > cnt_hi1 = C(lo + 2^shift)
    unsigned lo = 0u, cnt_lo = F_DIM, cnt_hi1 = 0u;
    int shift = 32;

    // ---- 2-bit multiway count sweeps (row re-read from L1/L2 each sweep) ----
    #pragma unroll 1
    while (cnt_lo - cnt_hi1 > CAP && shift > 0) {
        unsigned q = 1u << (shift - 2);
        unsigned t1 = lo + q, t2 = lo + 2u * q, t3 = lo + 3u * q;
        unsigned c1 = 0, c2 = 0, c3 = 0;
        {
            uint4 a0, a1, a2, a3; load_row(xr, tid, a0, a1, a2, a3);
            unsigned key[16]; to_keys(a0, a1, a2, a3, key);
            #pragma unroll
            for (int e = 0; e < 16; ++e) {
                c1 += (key[e] >= t1);
                c2 += (key[e] >= t2);
                c3 += (key[e] >= t3);
            }
        }
        c1 = __reduce_add_sync(0xffffffffu, c1);
        c2 = __reduce_add_sync(0xffffffffu, c2);
        c3 = __reduce_add_sync(0xffffffffu, c3);
        if (lane == 0) { s_warp[wid][0] = c1; s_warp[wid][1] = c2; s_warp[wid][2] = c3; }
        __syncthreads();
        unsigned C1 = 0, C2 = 0, C3 = 0;
        #pragma unroll
        for (int u2 = 0; u2 < 8; ++u2) { C1 += s_warp[u2][0]; C2 += s_warp[u2][1]; C3 += s_warp[u2][2]; }
        __syncthreads();
        if      (C3 >= K) { lo = t3; cnt_lo = C3; }
        else if (C2 >= K) { lo = t2; cnt_lo = C2; cnt_hi1 = C3; }
        else if (C1 >= K) { lo = t1; cnt_lo = C1; cnt_hi1 = C2; }
        else              {                      cnt_hi1 = C1; }
        shift -= 2;
    }

    unsigned Kstar, c_ge, c_gt;
    if (shift == 0) {
        // width-1 bracket: exact (heavy-ties fallback)
        Kstar = lo; c_ge = cnt_lo; c_gt = cnt_hi1;
    } else {
        // ---- compact candidates (keys in [lo, hi]) into smem ----
        if (tid == 0) s_ctrl[7] = 0u;
        __syncthreads();
        const unsigned hi = lo + ((1u << shift) - 1u);
        {
            uint4 a0, a1, a2, a3; load_row(xr, tid, a0, a1, a2, a3);
            unsigned key[16]; to_keys(a0, a1, a2, a3, key);
            #pragma unroll
            for (int e = 0; e < 16; ++e) {
                bool in = (key[e] >= lo) && (key[e] <= hi);
                unsigned m = __ballot_sync(0xffffffffu, in);
                unsigned base = 0u;
                if (lane == 0) base = atomicAdd(&s_ctrl[7], (unsigned)__popc(m));
                base = __shfl_sync(0xffffffffu, base, 0);
                if (in) {
                    unsigned p = base + (unsigned)__popc(m & ((1u << lane) - 1u));
                    if (p < CAP) s_ckey[p] = key[e];
                }
            }
        }
        __syncthreads();

        // ---- block-parallel rank selection over <=128 candidates ----
        const unsigned n_c = s_ctrl[7];          // == cnt_lo - cnt_hi1 <= CAP
        const unsigned A   = cnt_hi1;            // count strictly above bracket
        if ((unsigned)tid < n_c) {
            unsigned c = s_ckey[tid];
            unsigned gt = 0, ge = 0;
            #pragma unroll 4
            for (unsigned j = 0; j < n_c; ++j) {
                unsigned v = s_ckey[j];
                gt += (v >  c);
                ge += (v >= c);
            }
            unsigned GT = A + gt, GE = A + ge;
            if (GT < K && GE >= K) {             // exactly the candidates equal to Kstar
                s_ctrl[0] = c; s_ctrl[2] = GE; s_ctrl[3] = GT;
            }
        }
        __syncthreads();
        Kstar = s_ctrl[0]; c_ge = s_ctrl[2]; c_gt = s_ctrl[3];
    }

    // ---- tie truncation (rare): keep lowest-index equals only ----
    unsigned Ccut = 0xFFFFFFFFu;
    {
        unsigned budget = K - c_gt;              // >= 1
        unsigned c_eq   = c_ge - c_gt;           // >= budget
        if (budget < c_eq) {
            int loB = 0, hiB = F_DIM - 1;
            #pragma unroll 1
            while (loB < hiB) {
                int mid = (loB + hiB) >> 1;
                unsigned c = 0;
                {
                    uint4 a0, a1, a2, a3; load_row(xr, tid, a0, a1, a2, a3);
                    unsigned key[16]; to_keys(a0, a1, a2, a3, key);
                    #pragma unroll
                    for (int e = 0; e < 16; ++e) {
                        int col = ((e >> 2) << 10) + (tid << 2) + (e & 3);
                        c += (key[e] == Kstar && col <= mid) ? 1u : 0u;
                    }
                }
                c = __reduce_add_sync(0xffffffffu, c);
                if (lane == 0) s_warp[wid][0] = c;
                __syncthreads();
                unsigned Ct = 0;
                #pragma unroll
                for (int u2 = 0; u2 < 8; ++u2) Ct += s_warp[u2][0];
                __syncthreads();
                if (Ct >= budget) hiB = mid; else loB = mid + 1;
            }
            Ccut = (unsigned)loB;
        }
    }

    // ---- write: keep iff key > Kstar, or key == Kstar and col <= Ccut ----
    {
        uint4 a0, a1, a2, a3; load_row(xr, tid, a0, a1, a2, a3);
        uint4 av[4] = {a0, a1, a2, a3};
        #pragma unroll
        for (int i = 0; i < 4; ++i) {
            unsigned col0 = (unsigned)((i << 10) + (tid << 2));
            unsigned u0 = av[i].x, u1 = av[i].y, u2v = av[i].z, u3 = av[i].w;
            unsigned k0 = f2key(u0), k1 = f2key(u1), k2 = f2key(u2v), k3 = f2key(u3);
            uint4 v;
            v.x = ((k0 > Kstar) || (k0 == Kstar && (col0 + 0u) <= Ccut)) ? u0  : 0u;
            v.y = ((k1 > Kstar) || (k1 == Kstar && (col0 + 1u) <= Ccut)) ? u1  : 0u;
            v.z = ((k2 > Kstar) || (k2 == Kstar && (col0 + 2u) <= Ccut)) ? u2v : 0u;
            v.w = ((k3 > Kstar) || (k3 == Kstar && (col0 + 3u) <= Ccut)) ? u3  : 0u;
            orow[tid + i * 256] = v;
        }
    }
}

extern "C" void kernel_launch(void* const* d_in, const int* in_sizes, int n_in,
                              void* d_out, int out_size)
{
    const float* x  = (const float*)d_in[0];
    const int*   kp = (n_in >= 2) ? (const int*)d_in[1] : nullptr;
    float* out = (float*)d_out;

    int B = in_sizes[0] / F_DIM;
    topk_mask_kernel<<<B, TPB>>>(x, kp, 64, out);
}

// round 5
// speedup vs baseline: 2.6637x; 1.9823x over previous
#include <cuda_runtime.h>
#include <stdint.h>

// TopK mask: out = x * (x in top-k of its row), ties -> lowest index.
// One CTA (256 thr) per row of 4096 fp32.
// R5 fast path (float domain, no key conversion):
//   pass1: count+compact candidates x >= 2.0f (atomic-free prefix compaction)
//   rank : gt-only O(n) scan per candidate, winner has gt == K-1
//   write: FSETP/FSEL masked store
// Exact fallbacks: duplicate-at-threshold -> min-col tie cut; anything else
// (wrong distribution, straddling ties, k!=64 shapes) -> general key-domain
// radix select (R4 algorithm), bit-exact.

#define F_DIM 4096
#define TPB   256
#define CAP   192   // candidate capacity (count(x>=2.0) ~ 93 +- 9.5)

static __device__ __forceinline__ unsigned f2key(unsigned u) {
    return u ^ ((unsigned)((int)u >> 31) | 0x80000000u);
}

static __device__ __forceinline__ void load_rowf(const float4* __restrict__ xr, int tid,
                                                 float4& a0, float4& a1, float4& a2, float4& a3) {
    a0 = __ldg(xr + tid);
    a1 = __ldg(xr + tid + 256);
    a2 = __ldg(xr + tid + 512);
    a3 = __ldg(xr + tid + 768);
}

__global__ __launch_bounds__(TPB, 6)
void topk_mask_kernel(const float* __restrict__ x,
                      const int*   __restrict__ kptr,
                      int kfallback,
                      float* __restrict__ out)
{
    const int tid  = threadIdx.x;
    const int lane = tid & 31;
    const int wid  = tid >> 5;
    const size_t row = blockIdx.x;

    __shared__ __align__(16) float s_cand[CAP + 2];   // fast: floats; general: keys
    __shared__ unsigned s_wcnt[8];
    __shared__ unsigned s_warp[8][4];
    __shared__ unsigned s_ctrl[8];   // [0]=Kstar bits [1]=winner cnt [2]=c_ge [3]=c_gt [7]=cand ctr

    const float4* __restrict__ xr   = reinterpret_cast<const float4*>(x) + row * (F_DIM / 4);
    float4*       __restrict__ orow = reinterpret_cast<float4*>(out)     + row * (F_DIM / 4);

    const int kv = (kptr != nullptr) ? *kptr : kfallback;

    if (kv <= 0) {
        float4 z; z.x = z.y = z.z = z.w = 0.0f;
        #pragma unroll
        for (int i = 0; i < 4; ++i) orow[tid + i * 256] = z;
        return;
    }
    if (kv >= F_DIM) {
        float4 a0, a1, a2, a3; load_rowf(xr, tid, a0, a1, a2, a3);
        orow[tid] = a0; orow[tid + 256] = a1; orow[tid + 512] = a2; orow[tid + 768] = a3;
        return;
    }
    const unsigned K = (unsigned)kv;

    // ================= FAST PATH: fixed threshold 2.0f =================
    const float T3 = 2.0f;
    unsigned n_c;
    {
        float4 a0, a1, a2, a3; load_rowf(xr, tid, a0, a1, a2, a3);
        float v[16] = { a0.x,a0.y,a0.z,a0.w, a1.x,a1.y,a1.z,a1.w,
                        a2.x,a2.y,a2.z,a2.w, a3.x,a3.y,a3.z,a3.w };
        // per-lane candidate count
        unsigned cnt = 0;
        #pragma unroll
        for (int e = 0; e < 16; ++e) cnt += (v[e] >= T3);
        // warp inclusive scan
        unsigned incl = cnt;
        #pragma unroll
        for (int d = 1; d < 32; d <<= 1) {
            unsigned nb = __shfl_up_sync(0xffffffffu, incl, d);
            if (lane >= d) incl += nb;
        }
        unsigned wtot = __shfl_sync(0xffffffffu, incl, 31);
        if (lane == 0) s_wcnt[wid] = wtot;
        if (tid == 0)  s_ctrl[1] = 0u;
        __syncthreads();
        unsigned base = 0, tot = 0;
        #pragma unroll
        for (int w = 0; w < 8; ++w) {
            unsigned t = s_wcnt[w];
            tot += t;
            if (w < wid) base += t;
        }
        n_c = tot;
        unsigned pos = base + (incl - cnt);
        #pragma unroll
        for (int e = 0; e < 16; ++e) {
            if (v[e] >= T3) {
                if (pos < CAP) s_cand[pos] = v[e];
                ++pos;
            }
        }
        if (tid == 0 && n_c < CAP) {           // pad for float2 pair loads
            s_cand[n_c]     = __int_as_float(0xff800000);   // -inf
            s_cand[n_c + 1] = __int_as_float(0xff800000);
        }
    }
    __syncthreads();

    if (n_c >= K && n_c <= CAP) {
        // ---- gt-only rank scan: winner has exactly K-1 candidates above it ----
        float c = 0.0f;
        unsigned gt = 0;
        if ((unsigned)tid < n_c) {
            c = s_cand[tid];
            const float2* p2 = reinterpret_cast<const float2*>(s_cand);
            const unsigned np = (n_c + 1u) >> 1;
            #pragma unroll 4
            for (unsigned jp = 0; jp < np; ++jp) {
                float2 w2 = p2[jp];
                gt += (w2.x > c);
                gt += (w2.y > c);
            }
            if (gt == K - 1u) {
                atomicAdd(&s_ctrl[1], 1u);
                s_ctrl[0] = __float_as_uint(c);   // dups write identical bits
            }
        }
        __syncthreads();
        const unsigned m = s_ctrl[1];
        if (m >= 1u) {
            const float Ks = __uint_as_float(s_ctrl[0]);
            unsigned Ccut = 0xFFFFFFFFu;
            if (m > 1u) {
                // budget = K - (K-1) = 1 -> keep only lowest-index element == Ks
                float4 a0, a1, a2, a3; load_rowf(xr, tid, a0, a1, a2, a3);
                float v[16] = { a0.x,a0.y,a0.z,a0.w, a1.x,a1.y,a1.z,a1.w,
                                a2.x,a2.y,a2.z,a2.w, a3.x,a3.y,a3.z,a3.w };
                unsigned mc = 0xFFFFFFFFu;
                #pragma unroll
                for (int e = 0; e < 16; ++e) {
                    unsigned col = (unsigned)(((e >> 2) << 10) + (tid << 2) + (e & 3));
                    if (v[e] == Ks) mc = min(mc, col);
                }
                mc = __reduce_min_sync(0xffffffffu, mc);
                if (lane == 0) s_warp[wid][0] = mc;
                __syncthreads();
                unsigned mm = 0xFFFFFFFFu;
                #pragma unroll
                for (int w = 0; w < 8; ++w) mm = min(mm, s_warp[w][0]);
                Ccut = mm;
            }
            // ---- write ----
            float4 a0, a1, a2, a3; load_rowf(xr, tid, a0, a1, a2, a3);
            float4 av[4] = {a0, a1, a2, a3};
            if (Ccut == 0xFFFFFFFFu) {
                #pragma unroll
                for (int i = 0; i < 4; ++i) {
                    float4 v4 = av[i], o;
                    o.x = (v4.x >= Ks) ? v4.x : 0.0f;
                    o.y = (v4.y >= Ks) ? v4.y : 0.0f;
                    o.z = (v4.z >= Ks) ? v4.z : 0.0f;
                    o.w = (v4.w >= Ks) ? v4.w : 0.0f;
                    orow[tid + i * 256] = o;
                }
            } else {
                #pragma unroll
                for (int i = 0; i < 4; ++i) {
                    unsigned col0 = (unsigned)((i << 10) + (tid << 2));
                    float4 v4 = av[i], o;
                    o.x = ((v4.x > Ks) || (v4.x == Ks && (col0 + 0u) <= Ccut)) ? v4.x : 0.0f;
                    o.y = ((v4.y > Ks) || (v4.y == Ks && (col0 + 1u) <= Ccut)) ? v4.y : 0.0f;
                    o.z = ((v4.z > Ks) || (v4.z == Ks && (col0 + 2u) <= Ccut)) ? v4.z : 0.0f;
                    o.w = ((v4.w > Ks) || (v4.w == Ks && (col0 + 3u) <= Ccut)) ? v4.w : 0.0f;
                    orow[tid + i * 256] = o;
                }
            }
            return;
        }
        // m == 0: tie group straddles K -> general path below
    }

    // ================= GENERAL PATH (exact, key domain, rare) =================
    __syncthreads();
    unsigned* s_ckey = reinterpret_cast<unsigned*>(s_cand);
    const uint4* __restrict__ xu = reinterpret_cast<const uint4*>(x) + row * (F_DIM / 4);

    unsigned lo = 0u, cnt_lo = F_DIM, cnt_hi1 = 0u;
    int shift = 32;

    #pragma unroll 1
    while (cnt_lo - cnt_hi1 > CAP && shift > 0) {
        unsigned q = 1u << (shift - 2);
        unsigned t1 = lo + q, t2 = lo + 2u * q, t3 = lo + 3u * q;
        unsigned c1 = 0, c2 = 0, c3 = 0;
        {
            uint4 b0 = __ldg(xu + tid), b1 = __ldg(xu + tid + 256),
                  b2 = __ldg(xu + tid + 512), b3 = __ldg(xu + tid + 768);
            unsigned key[16] = { f2key(b0.x),f2key(b0.y),f2key(b0.z),f2key(b0.w),
                                 f2key(b1.x),f2key(b1.y),f2key(b1.z),f2key(b1.w),
                                 f2key(b2.x),f2key(b2.y),f2key(b2.z),f2key(b2.w),
                                 f2key(b3.x),f2key(b3.y),f2key(b3.z),f2key(b3.w) };
            #pragma unroll
            for (int e = 0; e < 16; ++e) {
                c1 += (key[e] >= t1);
                c2 += (key[e] >= t2);
                c3 += (key[e] >= t3);
            }
        }
        c1 = __reduce_add_sync(0xffffffffu, c1);
        c2 = __reduce_add_sync(0xffffffffu, c2);
        c3 = __reduce_add_sync(0xffffffffu, c3);
        if (lane == 0) { s_warp[wid][0] = c1; s_warp[wid][1] = c2; s_warp[wid][2] = c3; }
        __syncthreads();
        unsigned C1 = 0, C2 = 0, C3 = 0;
        #pragma unroll
        for (int w = 0; w < 8; ++w) { C1 += s_warp[w][0]; C2 += s_warp[w][1]; C3 += s_warp[w][2]; }
        __syncthreads();
        if      (C3 >= K) { lo = t3; cnt_lo = C3; }
        else if (C2 >= K) { lo = t2; cnt_lo = C2; cnt_hi1 = C3; }
        else if (C1 >= K) { lo = t1; cnt_lo = C1; cnt_hi1 = C2; }
        else              {                      cnt_hi1 = C1; }
        shift -= 2;
    }

    unsigned Kstar, c_ge, c_gt;
    if (shift == 0) {
        Kstar = lo; c_ge = cnt_lo; c_gt = cnt_hi1;
    } else {
        if (tid == 0) s_ctrl[7] = 0u;
        __syncthreads();
        const unsigned hib = lo + ((1u << shift) - 1u);
        {
            uint4 b0 = __ldg(xu + tid), b1 = __ldg(xu + tid + 256),
                  b2 = __ldg(xu + tid + 512), b3 = __ldg(xu + tid + 768);
            unsigned key[16] = { f2key(b0.x),f2key(b0.y),f2key(b0.z),f2key(b0.w),
                                 f2key(b1.x),f2key(b1.y),f2key(b1.z),f2key(b1.w),
                                 f2key(b2.x),f2key(b2.y),f2key(b2.z),f2key(b2.w),
                                 f2key(b3.x),f2key(b3.y),f2key(b3.z),f2key(b3.w) };
            #pragma unroll
            for (int e = 0; e < 16; ++e) {
                bool in = (key[e] >= lo) && (key[e] <= hib);
                unsigned mk = __ballot_sync(0xffffffffu, in);
                unsigned base = 0u;
                if (lane == 0) base = atomicAdd(&s_ctrl[7], (unsigned)__popc(mk));
                base = __shfl_sync(0xffffffffu, base, 0);
                if (in) {
                    unsigned p = base + (unsigned)__popc(mk & ((1u << lane) - 1u));
                    if (p < CAP) s_ckey[p] = key[e];
                }
            }
        }
        __syncthreads();

        const unsigned nc = s_ctrl[7];
        const unsigned A  = cnt_hi1;
        if ((unsigned)tid < nc) {
            unsigned ck = s_ckey[tid];
            unsigned gt = 0, ge = 0;
            #pragma unroll 4
            for (unsigned j = 0; j < nc; ++j) {
                unsigned vv = s_ckey[j];
                gt += (vv >  ck);
                ge += (vv >= ck);
            }
            unsigned GT = A + gt, GE = A + ge;
            if (GT < K && GE >= K) { s_ctrl[0] = ck; s_ctrl[2] = GE; s_ctrl[3] = GT; }
        }
        __syncthreads();
        Kstar = s_ctrl[0]; c_ge = s_ctrl[2]; c_gt = s_ctrl[3];
    }

    unsigned Ccut = 0xFFFFFFFFu;
    {
        unsigned budget = K - c_gt;
        unsigned c_eq   = c_ge - c_gt;
        if (budget < c_eq) {
            int loB = 0, hiB = F_DIM - 1;
            #pragma unroll 1
            while (loB < hiB) {
                int mid = (loB + hiB) >> 1;
                unsigned cc = 0;
                {
                    uint4 b0 = __ldg(xu + tid), b1 = __ldg(xu + tid + 256),
                          b2 = __ldg(xu + tid + 512), b3 = __ldg(xu + tid + 768);
                    unsigned key[16] = { f2key(b0.x),f2key(b0.y),f2key(b0.z),f2key(b0.w),
                                         f2key(b1.x),f2key(b1.y),f2key(b1.z),f2key(b1.w),
                                         f2key(b2.x),f2key(b2.y),f2key(b2.z),f2key(b2.w),
                                         f2key(b3.x),f2key(b3.y),f2key(b3.z),f2key(b3.w) };
                    #pragma unroll
                    for (int e = 0; e < 16; ++e) {
                        int col = ((e >> 2) << 10) + (tid << 2) + (e & 3);
                        cc += (key[e] == Kstar && col <= mid) ? 1u : 0u;
                    }
                }
                cc = __reduce_add_sync(0xffffffffu, cc);
                if (lane == 0) s_warp[wid][0] = cc;
                __syncthreads();
                unsigned Ct = 0;
                #pragma unroll
                for (int w = 0; w < 8; ++w) Ct += s_warp[w][0];
                __syncthreads();
                if (Ct >= budget) hiB = mid; else loB = mid + 1;
            }
            Ccut = (unsigned)loB;
        }
    }

    {
        uint4 b0 = __ldg(xu + tid), b1 = __ldg(xu + tid + 256),
              b2 = __ldg(xu + tid + 512), b3 = __ldg(xu + tid + 768);
        uint4 bv[4] = {b0, b1, b2, b3};
        uint4* ou = reinterpret_cast<uint4*>(orow);
        #pragma unroll
        for (int i = 0; i < 4; ++i) {
            unsigned col0 = (unsigned)((i << 10) + (tid << 2));
            unsigned u0 = bv[i].x, u1 = bv[i].y, u2v = bv[i].z, u3 = bv[i].w;
            unsigned k0 = f2key(u0), k1 = f2key(u1), k2 = f2key(u2v), k3 = f2key(u3);
            uint4 o;
            o.x = ((k0 > Kstar) || (k0 == Kstar && (col0 + 0u) <= Ccut)) ? u0  : 0u;
            o.y = ((k1 > Kstar) || (k1 == Kstar && (col0 + 1u) <= Ccut)) ? u1  : 0u;
            o.z = ((k2 > Kstar) || (k2 == Kstar && (col0 + 2u) <= Ccut)) ? u2v : 0u;
            o.w = ((k3 > Kstar) || (k3 == Kstar && (col0 + 3u) <= Ccut)) ? u3  : 0u;
            ou[tid + i * 256] = o;
        }
    }
}

extern "C" void kernel_launch(void* const* d_in, const int* in_sizes, int n_in,
                              void* d_out, int out_size)
{
    const float* x  = (const float*)d_in[0];
    const int*   kp = (n_in >= 2) ? (const int*)d_in[1] : nullptr;
    float* out = (float*)d_out;

    int B = in_sizes[0] / F_DIM;
    topk_mask_kernel<<<B, TPB>>>(x, kp, 64, out);
}